// round 7
// baseline (speedup 1.0000x reference)
#include <cuda_runtime.h>
#include <cuda_bf16.h>

// Seq2Seq stacked GRU (L=64, H=64, D=128, B=128, T=256), wavefront-pipelined.
//  K1: precompute layer-0 input projections gi0 = x @ Wih0^T + bih0 (enc+dec)
//  K2: persistent wavefront kernel: 128 CTAs = 64 layers x 2 batch halves,
//      weights in SMEM, neighbor flag sync through L2, ring-buffered acts.
//  K3: output projection out = dec_top @ Wo^T + bo.

#define Hn    64
#define Ln    64
#define Dn    128
#define Bn    128
#define Tn    256
#define G3H   192
#define RINGN 4          // ring depth (power of two)
#define WSTR  194        // padded SMEM stride for transposed weights (even)
#define HB    64         // batch rows per CTA (half of B)

// Static device scratch (allocation-free rule: __device__ globals only)
__device__ float g_gi0[2][Tn][Bn][G3H];          // ~50 MB
__device__ float g_xbuf[Ln][2][RINGN][HB][Hn];   // inter-layer ring, ~8.4 MB
__device__ float g_dectop[Tn][Bn][Hn];           // decoder top outputs, ~8.4 MB
__device__ int   g_prog[Ln * 2];                 // monotone progress counters

__device__ __forceinline__ float sigf(float x) {
    return __fdividef(1.0f, 1.0f + __expf(-x));
}
__device__ __forceinline__ float tanhf_fast(float x) {
    return __fdividef(2.0f, 1.0f + __expf(-2.0f * x)) - 1.0f;
}

// ---------------------------------------------------------------------------
// Kernel 1: gi0 for layer 0 of both GRUs. grid = (T, 2 halves, 2 models).
// ---------------------------------------------------------------------------
#define GI0_SMEM ((Dn * WSTR + HB * Dn) * 4)

__global__ void __launch_bounds__(256, 1) gi0_kernel(
    const float* __restrict__ ctx,
    const float* __restrict__ encW0, const float* __restrict__ decW0,
    const float* __restrict__ encB,  const float* __restrict__ decB)
{
    extern __shared__ float sm[];
    float* W_s = sm;                 // [Dn][WSTR] transposed: W_s[k*WSTR + j]
    float* x_s = W_s + Dn * WSTR;    // [HB][Dn]

    const int t = blockIdx.x, half = blockIdx.y, m = blockIdx.z;
    const float* W0 = m ? decW0 : encW0;
    const float* bi = m ? decB  : encB;     // layer-0 bias row at offset 0
    const int tid = threadIdx.x;
    const int warp = tid >> 5, lane = tid & 31;
    const int bb = warp * 8, jj = lane * 2;

    for (int idx = tid; idx < G3H * Dn; idx += 256) {
        int j = idx >> 7, k = idx & 127;
        W_s[k * WSTR + j] = W0[idx];
    }
    const int tt = m ? (t - 1) : t;
    if (m && t == 0) {
        for (int idx = tid; idx < HB * Dn; idx += 256) x_s[idx] = 0.f;
    } else {
        for (int idx = tid; idx < HB * Dn; idx += 256) {
            int b = idx >> 7, k = idx & 127;
            x_s[idx] = ctx[((size_t)(half * HB + b) * Tn + tt) * Dn + k];
        }
    }
    __syncthreads();

    float ar[8][2], az[8][2], an[8][2];
#pragma unroll
    for (int i = 0; i < 8; i++) {
        ar[i][0] = ar[i][1] = az[i][0] = az[i][1] = an[i][0] = an[i][1] = 0.f;
    }

    for (int k0 = 0; k0 < Dn; k0 += 4) {
        float2 wr[4], wz[4], wn[4];
#pragma unroll
        for (int kk = 0; kk < 4; kk++) {
            const float* wrow = &W_s[(k0 + kk) * WSTR];
            wr[kk] = *(const float2*)&wrow[jj];
            wz[kk] = *(const float2*)&wrow[64 + jj];
            wn[kk] = *(const float2*)&wrow[128 + jj];
        }
#pragma unroll
        for (int i = 0; i < 8; i++) {
            float4 xv = *(const float4*)&x_s[(bb + i) * Dn + k0];
            float xk[4] = {xv.x, xv.y, xv.z, xv.w};
#pragma unroll
            for (int kk = 0; kk < 4; kk++) {
                ar[i][0] = fmaf(xk[kk], wr[kk].x, ar[i][0]);
                ar[i][1] = fmaf(xk[kk], wr[kk].y, ar[i][1]);
                az[i][0] = fmaf(xk[kk], wz[kk].x, az[i][0]);
                az[i][1] = fmaf(xk[kk], wz[kk].y, az[i][1]);
                an[i][0] = fmaf(xk[kk], wn[kk].x, an[i][0]);
                an[i][1] = fmaf(xk[kk], wn[kk].y, an[i][1]);
            }
        }
    }
    float2 br = *(const float2*)&bi[jj];
    float2 bz = *(const float2*)&bi[64 + jj];
    float2 bn = *(const float2*)&bi[128 + jj];
#pragma unroll
    for (int i = 0; i < 8; i++) {
        int bg = half * HB + bb + i;
        float* dst = &g_gi0[m][t][bg][0];
        *(float2*)&dst[jj]       = make_float2(ar[i][0] + br.x, ar[i][1] + br.y);
        *(float2*)&dst[64 + jj]  = make_float2(az[i][0] + bz.x, az[i][1] + bz.y);
        *(float2*)&dst[128 + jj] = make_float2(an[i][0] + bn.x, an[i][1] + bn.y);
    }
}

// ---------------------------------------------------------------------------
// Kernel 2: persistent wavefront GRU stack (encoder then decoder).
// ---------------------------------------------------------------------------
#define WAVE_SMEM ((Hn * WSTR * 2 + HB * Hn + HB * G3H + 4 * Hn) * 4)

__device__ __forceinline__ void stage_weights(
    float* Wih_s, float* Whh_s, float* cr_s, float* cz_s,
    float* bin_s, float* bhn_s,
    const float* __restrict__ Wih, const float* __restrict__ Whh,
    const float* __restrict__ bih, const float* __restrict__ bhh,
    int layer, bool isL0, int tid)
{
    if (!isL0) {
        const float* src = Wih + (size_t)(layer - 1) * G3H * Hn;
        for (int idx = tid; idx < G3H * Hn; idx += 256) {
            int j = idx >> 6, k = idx & 63;
            Wih_s[k * WSTR + j] = src[idx];
        }
    }
    const float* srch = Whh + (size_t)layer * G3H * Hn;
    for (int idx = tid; idx < G3H * Hn; idx += 256) {
        int j = idx >> 6, k = idx & 63;
        Whh_s[k * WSTR + j] = srch[idx];
    }
    if (tid < Hn) {
        int hj = tid;
        const float* bi = bih + layer * G3H;
        const float* bh = bhh + layer * G3H;
        cr_s[hj]  = (isL0 ? 0.f : bi[hj])      + bh[hj];
        cz_s[hj]  = (isL0 ? 0.f : bi[64 + hj]) + bh[64 + hj];
        bin_s[hj] = (isL0 ? 0.f : bi[128 + hj]);
        bhn_s[hj] = bh[128 + hj];
    }
}

__global__ void __launch_bounds__(256, 1) gru_wave(
    const float* __restrict__ encWih, const float* __restrict__ encWhh,
    const float* __restrict__ encBih, const float* __restrict__ encBhh,
    const float* __restrict__ decWih, const float* __restrict__ decWhh,
    const float* __restrict__ decBih, const float* __restrict__ decBhh)
{
    extern __shared__ float sm[];
    float* Wih_s = sm;                       // [64][WSTR]
    float* Whh_s = Wih_s + Hn * WSTR;        // [64][WSTR]
    float* h_s   = Whh_s + Hn * WSTR;        // [HB][Hn]
    float* x_s   = h_s + HB * Hn;            // [HB][Hn] or gi0 [HB][G3H] (l0)
    float* cr_s  = x_s + HB * G3H;
    float* cz_s  = cr_s + Hn;
    float* bin_s = cz_s + Hn;
    float* bhn_s = bin_s + Hn;

    const int tid   = threadIdx.x;
    const int cta   = blockIdx.x;
    const int layer = cta >> 1;
    const int half  = cta & 1;
    const bool isL0 = (layer == 0);
    const int warp = tid >> 5, lane = tid & 31;
    const int bb = warp * 8;
    const int jj = lane * 2;

    int base = 0;
    if (tid == 0) base = *(volatile int*)&g_prog[cta];

    for (int i = tid; i < HB * Hn; i += 256) h_s[i] = 0.f;   // h0 = 0
    stage_weights(Wih_s, Whh_s, cr_s, cz_s, bin_s, bhn_s,
                  encWih, encWhh, encBih, encBhh, layer, isL0, tid);
    __syncthreads();

    for (int t = 0; t < 2 * Tn; ++t) {
        if (t == Tn) {   // encoder -> decoder: swap weights, keep h (= h_n)
            __syncthreads();
            stage_weights(Wih_s, Whh_s, cr_s, cz_s, bin_s, bhn_s,
                          decWih, decWhh, decBih, decBhh, layer, isL0, tid);
            __syncthreads();
        }
        // ---- sync: producer data ready / consumer slot free ----
        if (tid == 0) {
            if (layer > 0) {
                int tgt = base + t + 1;
                volatile int* p = &g_prog[cta - 2];
                while (*p < tgt) __nanosleep(64);
            }
            if (layer < Ln - 1 && t >= RINGN) {
                int tgt = base + t - RINGN + 1;
                volatile int* p = &g_prog[cta + 2];
                while (*p < tgt) __nanosleep(64);
            }
            __threadfence();
        }
        __syncthreads();

        // ---- stage input ----
        if (isL0) {
            int m  = (t < Tn) ? 0 : 1;
            int tt = (t < Tn) ? t : t - Tn;
            const float4* src = (const float4*)&g_gi0[m][tt][half * HB][0];
            float4* dst = (float4*)x_s;
            for (int i = tid; i < HB * G3H / 4; i += 256) dst[i] = src[i];
        } else {
            const float4* src =
                (const float4*)&g_xbuf[layer - 1][half][t & (RINGN - 1)][0][0];
            float4* dst = (float4*)x_s;
            for (int i = tid; i < HB * Hn / 4; i += 256) dst[i] = __ldcv(&src[i]);
        }
        __syncthreads();

        // ---- GEMMs ----
        float ar[8][2], az[8][2], ain[8][2], ahn[8][2];
#pragma unroll
        for (int i = 0; i < 8; i++) {
            ar[i][0] = ar[i][1] = az[i][0] = az[i][1] = 0.f;
            ain[i][0] = ain[i][1] = ahn[i][0] = ahn[i][1] = 0.f;
        }

        if (!isL0) {
            for (int k0 = 0; k0 < Hn; k0 += 4) {
                float2 wr[4], wz[4], wn[4], ur[4], uz[4], un[4];
#pragma unroll
                for (int kk = 0; kk < 4; kk++) {
                    const float* a = &Wih_s[(k0 + kk) * WSTR];
                    const float* b = &Whh_s[(k0 + kk) * WSTR];
                    wr[kk] = *(const float2*)&a[jj];
                    wz[kk] = *(const float2*)&a[64 + jj];
                    wn[kk] = *(const float2*)&a[128 + jj];
                    ur[kk] = *(const float2*)&b[jj];
                    uz[kk] = *(const float2*)&b[64 + jj];
                    un[kk] = *(const float2*)&b[128 + jj];
                }
#pragma unroll
                for (int i = 0; i < 8; i++) {
                    float4 xv = *(const float4*)&x_s[(bb + i) * Hn + k0];
                    float4 hv = *(const float4*)&h_s[(bb + i) * Hn + k0];
                    float xk[4] = {xv.x, xv.y, xv.z, xv.w};
                    float hk[4] = {hv.x, hv.y, hv.z, hv.w};
#pragma unroll
                    for (int kk = 0; kk < 4; kk++) {
                        ar[i][0] = fmaf(xk[kk], wr[kk].x, ar[i][0]);
                        ar[i][0] = fmaf(hk[kk], ur[kk].x, ar[i][0]);
                        ar[i][1] = fmaf(xk[kk], wr[kk].y, ar[i][1]);
                        ar[i][1] = fmaf(hk[kk], ur[kk].y, ar[i][1]);
                        az[i][0] = fmaf(xk[kk], wz[kk].x, az[i][0]);
                        az[i][0] = fmaf(hk[kk], uz[kk].x, az[i][0]);
                        az[i][1] = fmaf(xk[kk], wz[kk].y, az[i][1]);
                        az[i][1] = fmaf(hk[kk], uz[kk].y, az[i][1]);
                        ain[i][0] = fmaf(xk[kk], wn[kk].x, ain[i][0]);
                        ain[i][1] = fmaf(xk[kk], wn[kk].y, ain[i][1]);
                        ahn[i][0] = fmaf(hk[kk], un[kk].x, ahn[i][0]);
                        ahn[i][1] = fmaf(hk[kk], un[kk].y, ahn[i][1]);
                    }
                }
            }
        } else {
            // layer 0: only h @ Whh^T (gi precomputed into x_s)
            for (int k0 = 0; k0 < Hn; k0 += 4) {
                float2 ur[4], uz[4], un[4];
#pragma unroll
                for (int kk = 0; kk < 4; kk++) {
                    const float* b = &Whh_s[(k0 + kk) * WSTR];
                    ur[kk] = *(const float2*)&b[jj];
                    uz[kk] = *(const float2*)&b[64 + jj];
                    un[kk] = *(const float2*)&b[128 + jj];
                }
#pragma unroll
                for (int i = 0; i < 8; i++) {
                    float4 hv = *(const float4*)&h_s[(bb + i) * Hn + k0];
                    float hk[4] = {hv.x, hv.y, hv.z, hv.w};
#pragma unroll
                    for (int kk = 0; kk < 4; kk++) {
                        ar[i][0] = fmaf(hk[kk], ur[kk].x, ar[i][0]);
                        ar[i][1] = fmaf(hk[kk], ur[kk].y, ar[i][1]);
                        az[i][0] = fmaf(hk[kk], uz[kk].x, az[i][0]);
                        az[i][1] = fmaf(hk[kk], uz[kk].y, az[i][1]);
                        ahn[i][0] = fmaf(hk[kk], un[kk].x, ahn[i][0]);
                        ahn[i][1] = fmaf(hk[kk], un[kk].y, ahn[i][1]);
                    }
                }
            }
        }
        __syncthreads();   // all reads of h_s done before update

        // ---- epilogue: gates, h update, publish ----
        const bool wring = (layer < Ln - 1);
        const bool wtop  = (layer == Ln - 1) && (t >= Tn);
        float* rdst = &g_xbuf[layer][half][t & (RINGN - 1)][0][0];
        float* tdst = wtop ? &g_dectop[t - Tn][half * HB][0] : rdst;

#pragma unroll
        for (int i = 0; i < 8; i++) {
            int b = bb + i;
#pragma unroll
            for (int p = 0; p < 2; p++) {
                int hj = jj + p;
                float xr, xz, xn;
                if (isL0) {
                    xr = x_s[b * G3H + hj];
                    xz = x_s[b * G3H + 64 + hj];
                    xn = x_s[b * G3H + 128 + hj];
                } else {
                    xr = 0.f; xz = 0.f; xn = ain[i][p];
                }
                float r = sigf(ar[i][p] + xr + cr_s[hj]);
                float z = sigf(az[i][p] + xz + cz_s[hj]);
                float n = tanhf_fast(xn + bin_s[hj] +
                                     r * (ahn[i][p] + bhn_s[hj]));
                float hold = h_s[b * Hn + hj];
                float hnew = (1.0f - z) * n + z * hold;
                h_s[b * Hn + hj] = hnew;
                if (wring) rdst[b * Hn + hj] = hnew;
                if (wtop)  tdst[b * Hn + hj] = hnew;
            }
        }
        __syncthreads();
        if (tid == 0) {
            __threadfence();
            *(volatile int*)&g_prog[cta] = base + t + 1;
        }
    }
}

// ---------------------------------------------------------------------------
// Kernel 3: output projection  out = dec_top @ Wo^T + bo. grid = (T, 2).
// ---------------------------------------------------------------------------
#define PSTR 130
#define PROJ_SMEM ((Hn * PSTR + HB * Hn) * 4)

__global__ void __launch_bounds__(256, 1) proj_kernel(
    const float* __restrict__ Wo, const float* __restrict__ bo,
    float* __restrict__ out)
{
    extern __shared__ float sm[];
    float* W_s = sm;                 // [64][PSTR] transposed: W_s[k*PSTR + d]
    float* x_s = W_s + Hn * PSTR;    // [HB][Hn]

    const int t = blockIdx.x, half = blockIdx.y;
    const int tid = threadIdx.x;
    const int warp = tid >> 5, lane = tid & 31;
    const int bb = warp * 8, jj = lane * 2;

    for (int idx = tid; idx < Dn * Hn; idx += 256) {
        int d = idx >> 6, k = idx & 63;
        W_s[k * PSTR + d] = Wo[idx];
    }
    for (int idx = tid; idx < HB * Hn; idx += 256) {
        x_s[idx] = g_dectop[t][half * HB + (idx >> 6)][idx & 63];
    }
    __syncthreads();

    float acc[8][4];
#pragma unroll
    for (int i = 0; i < 8; i++)
        acc[i][0] = acc[i][1] = acc[i][2] = acc[i][3] = 0.f;

    for (int k0 = 0; k0 < Hn; k0 += 4) {
        float2 w0[4], w1[4];
#pragma unroll
        for (int kk = 0; kk < 4; kk++) {
            const float* wrow = &W_s[(k0 + kk) * PSTR];
            w0[kk] = *(const float2*)&wrow[jj];
            w1[kk] = *(const float2*)&wrow[64 + jj];
        }
#pragma unroll
        for (int i = 0; i < 8; i++) {
            float4 xv = *(const float4*)&x_s[(bb + i) * Hn + k0];
            float xk[4] = {xv.x, xv.y, xv.z, xv.w};
#pragma unroll
            for (int kk = 0; kk < 4; kk++) {
                acc[i][0] = fmaf(xk[kk], w0[kk].x, acc[i][0]);
                acc[i][1] = fmaf(xk[kk], w0[kk].y, acc[i][1]);
                acc[i][2] = fmaf(xk[kk], w1[kk].x, acc[i][2]);
                acc[i][3] = fmaf(xk[kk], w1[kk].y, acc[i][3]);
            }
        }
    }
    float2 b0 = *(const float2*)&bo[jj];
    float2 b1 = *(const float2*)&bo[64 + jj];
#pragma unroll
    for (int i = 0; i < 8; i++) {
        int bg = half * HB + bb + i;
        float* o = &out[((size_t)bg * Tn + t) * Dn];
        *(float2*)&o[jj]      = make_float2(acc[i][0] + b0.x, acc[i][1] + b0.y);
        *(float2*)&o[64 + jj] = make_float2(acc[i][2] + b1.x, acc[i][3] + b1.y);
    }
}

// ---------------------------------------------------------------------------
extern "C" void kernel_launch(void* const* d_in, const int* in_sizes, int n_in,
                              void* d_out, int out_size) {
    const float* ctx     = (const float*)d_in[0];
    const float* encW0   = (const float*)d_in[1];
    const float* encWih  = (const float*)d_in[2];
    const float* encWhh  = (const float*)d_in[3];
    const float* encBih  = (const float*)d_in[4];
    const float* encBhh  = (const float*)d_in[5];
    const float* decW0   = (const float*)d_in[6];
    const float* decWih  = (const float*)d_in[7];
    const float* decWhh  = (const float*)d_in[8];
    const float* decBih  = (const float*)d_in[9];
    const float* decBhh  = (const float*)d_in[10];
    const float* Wo      = (const float*)d_in[11];
    const float* bo      = (const float*)d_in[12];
    float* out = (float*)d_out;

    cudaFuncSetAttribute(gi0_kernel,
        cudaFuncAttributeMaxDynamicSharedMemorySize, GI0_SMEM);
    cudaFuncSetAttribute(gru_wave,
        cudaFuncAttributeMaxDynamicSharedMemorySize, WAVE_SMEM);
    cudaFuncSetAttribute(proj_kernel,
        cudaFuncAttributeMaxDynamicSharedMemorySize, PROJ_SMEM);

    gi0_kernel<<<dim3(Tn, 2, 2), 256, GI0_SMEM>>>(ctx, encW0, decW0,
                                                  encBih, decBih);
    gru_wave<<<Ln * 2, 256, WAVE_SMEM>>>(encWih, encWhh, encBih, encBhh,
                                         decWih, decWhh, decBih, decBhh);
    proj_kernel<<<dim3(Tn, 2), 256, PROJ_SMEM>>>(Wo, bo, out);
}

// round 8
// speedup vs baseline: 1.0740x; 1.0740x over previous
#include <cuda_runtime.h>
#include <cuda_bf16.h>

// Seq2Seq stacked GRU (L=64, H=64, D=128, B=128, T=256), wavefront-pipelined.
//  K1: precompute layer-0 input projections gi0 = x @ Wih0^T + bih0 (enc+dec)
//  K2: persistent wavefront kernel: 128 CTAs = 64 layers x 2 batch halves,
//      weights in SMEM, neighbor flag sync through L2, ring-buffered acts.
//  K3: output projection out = dec_top @ Wo^T + bo.
// R7 change: all inner-product loops use packed fma.rn.f32x2 (FFMA2) --
// halves FMA-pipe issue count on the dominant (wave) kernel.

#define Hn    64
#define Ln    64
#define Dn    128
#define Bn    128
#define Tn    256
#define G3H   192
#define RINGN 4          // ring depth (power of two)
#define WSTR  194        // padded SMEM stride for transposed weights (even)
#define HB    64         // batch rows per CTA (half of B)

// Static device scratch (allocation-free rule: __device__ globals only)
__device__ float g_gi0[2][Tn][Bn][G3H];          // ~50 MB
__device__ float g_xbuf[Ln][2][RINGN][HB][Hn];   // inter-layer ring
__device__ float g_dectop[Tn][Bn][Hn];           // decoder top outputs
__device__ int   g_prog[Ln * 2];                 // monotone progress counters

__device__ __forceinline__ float sigf(float x) {
    return __fdividef(1.0f, 1.0f + __expf(-x));
}
__device__ __forceinline__ float tanhf_fast(float x) {
    return __fdividef(2.0f, 1.0f + __expf(-2.0f * x)) - 1.0f;
}

// ---- packed f32x2 helpers ------------------------------------------------
typedef unsigned long long u64;

__device__ __forceinline__ u64 pack2(float x) {
    u64 r;
    asm("mov.b64 %0, {%1, %1};" : "=l"(r) : "f"(x));
    return r;
}
__device__ __forceinline__ void fma2(u64& d, u64 a, u64 b) {
    asm("fma.rn.f32x2 %0, %1, %2, %0;" : "+l"(d) : "l"(a), "l"(b));
}
__device__ __forceinline__ float2 unpack2(u64 v) {
    float2 r;
    asm("mov.b64 {%0, %1}, %2;" : "=f"(r.x), "=f"(r.y) : "l"(v));
    return r;
}
// SMEM float2 load as b64 (addresses are 8B-aligned: even float offsets)
__device__ __forceinline__ u64 ld2(const float* p) {
    return *(const u64*)p;
}

// ---------------------------------------------------------------------------
// Kernel 1: gi0 for layer 0 of both GRUs. grid = (T, 2 halves, 2 models).
// ---------------------------------------------------------------------------
#define GI0_SMEM ((Dn * WSTR + HB * Dn) * 4)

__global__ void __launch_bounds__(256, 1) gi0_kernel(
    const float* __restrict__ ctx,
    const float* __restrict__ encW0, const float* __restrict__ decW0,
    const float* __restrict__ encB,  const float* __restrict__ decB)
{
    extern __shared__ float sm[];
    float* W_s = sm;                 // [Dn][WSTR] transposed: W_s[k*WSTR + j]
    float* x_s = W_s + Dn * WSTR;    // [HB][Dn]

    const int t = blockIdx.x, half = blockIdx.y, m = blockIdx.z;
    const float* W0 = m ? decW0 : encW0;
    const float* bi = m ? decB  : encB;     // layer-0 bias row at offset 0
    const int tid = threadIdx.x;
    const int warp = tid >> 5, lane = tid & 31;
    const int bb = warp * 8, jj = lane * 2;

    for (int idx = tid; idx < G3H * Dn; idx += 256) {
        int j = idx >> 7, k = idx & 127;
        W_s[k * WSTR + j] = W0[idx];
    }
    const int tt = m ? (t - 1) : t;
    if (m && t == 0) {
        for (int idx = tid; idx < HB * Dn; idx += 256) x_s[idx] = 0.f;
    } else {
        for (int idx = tid; idx < HB * Dn; idx += 256) {
            int b = idx >> 7, k = idx & 127;
            x_s[idx] = ctx[((size_t)(half * HB + b) * Tn + tt) * Dn + k];
        }
    }
    __syncthreads();

    u64 ar[8], az[8], an[8];
#pragma unroll
    for (int i = 0; i < 8; i++) { ar[i] = 0ull; az[i] = 0ull; an[i] = 0ull; }

    for (int k0 = 0; k0 < Dn; k0 += 4) {
        u64 wr[4], wz[4], wn[4];
#pragma unroll
        for (int kk = 0; kk < 4; kk++) {
            const float* wrow = &W_s[(k0 + kk) * WSTR];
            wr[kk] = ld2(&wrow[jj]);
            wz[kk] = ld2(&wrow[64 + jj]);
            wn[kk] = ld2(&wrow[128 + jj]);
        }
#pragma unroll
        for (int i = 0; i < 8; i++) {
            float4 xv = *(const float4*)&x_s[(bb + i) * Dn + k0];
            u64 xp[4] = {pack2(xv.x), pack2(xv.y), pack2(xv.z), pack2(xv.w)};
#pragma unroll
            for (int kk = 0; kk < 4; kk++) {
                fma2(ar[i], xp[kk], wr[kk]);
                fma2(az[i], xp[kk], wz[kk]);
                fma2(an[i], xp[kk], wn[kk]);
            }
        }
    }
    float2 br = *(const float2*)&bi[jj];
    float2 bz = *(const float2*)&bi[64 + jj];
    float2 bn = *(const float2*)&bi[128 + jj];
#pragma unroll
    for (int i = 0; i < 8; i++) {
        int bg = half * HB + bb + i;
        float* dst = &g_gi0[m][t][bg][0];
        float2 vr = unpack2(ar[i]), vz = unpack2(az[i]), vn = unpack2(an[i]);
        *(float2*)&dst[jj]       = make_float2(vr.x + br.x, vr.y + br.y);
        *(float2*)&dst[64 + jj]  = make_float2(vz.x + bz.x, vz.y + bz.y);
        *(float2*)&dst[128 + jj] = make_float2(vn.x + bn.x, vn.y + bn.y);
    }
}

// ---------------------------------------------------------------------------
// Kernel 2: persistent wavefront GRU stack (encoder then decoder).
// ---------------------------------------------------------------------------
#define WAVE_SMEM ((Hn * WSTR * 2 + HB * Hn + HB * G3H + 4 * Hn) * 4)

__device__ __forceinline__ void stage_weights(
    float* Wih_s, float* Whh_s, float* cr_s, float* cz_s,
    float* bin_s, float* bhn_s,
    const float* __restrict__ Wih, const float* __restrict__ Whh,
    const float* __restrict__ bih, const float* __restrict__ bhh,
    int layer, bool isL0, int tid)
{
    if (!isL0) {
        const float* src = Wih + (size_t)(layer - 1) * G3H * Hn;
        for (int idx = tid; idx < G3H * Hn; idx += 256) {
            int j = idx >> 6, k = idx & 63;
            Wih_s[k * WSTR + j] = src[idx];
        }
    }
    const float* srch = Whh + (size_t)layer * G3H * Hn;
    for (int idx = tid; idx < G3H * Hn; idx += 256) {
        int j = idx >> 6, k = idx & 63;
        Whh_s[k * WSTR + j] = srch[idx];
    }
    if (tid < Hn) {
        int hj = tid;
        const float* bi = bih + layer * G3H;
        const float* bh = bhh + layer * G3H;
        cr_s[hj]  = (isL0 ? 0.f : bi[hj])      + bh[hj];
        cz_s[hj]  = (isL0 ? 0.f : bi[64 + hj]) + bh[64 + hj];
        bin_s[hj] = (isL0 ? 0.f : bi[128 + hj]);
        bhn_s[hj] = bh[128 + hj];
    }
}

__global__ void __launch_bounds__(256, 1) gru_wave(
    const float* __restrict__ encWih, const float* __restrict__ encWhh,
    const float* __restrict__ encBih, const float* __restrict__ encBhh,
    const float* __restrict__ decWih, const float* __restrict__ decWhh,
    const float* __restrict__ decBih, const float* __restrict__ decBhh)
{
    extern __shared__ float sm[];
    float* Wih_s = sm;                       // [64][WSTR]
    float* Whh_s = Wih_s + Hn * WSTR;        // [64][WSTR]
    float* h_s   = Whh_s + Hn * WSTR;        // [HB][Hn]
    float* x_s   = h_s + HB * Hn;            // [HB][Hn] or gi0 [HB][G3H] (l0)
    float* cr_s  = x_s + HB * G3H;
    float* cz_s  = cr_s + Hn;
    float* bin_s = cz_s + Hn;
    float* bhn_s = bin_s + Hn;

    const int tid   = threadIdx.x;
    const int cta   = blockIdx.x;
    const int layer = cta >> 1;
    const int half  = cta & 1;
    const bool isL0 = (layer == 0);
    const int warp = tid >> 5, lane = tid & 31;
    const int bb = warp * 8;
    const int jj = lane * 2;

    int base = 0;
    if (tid == 0) base = *(volatile int*)&g_prog[cta];

    for (int i = tid; i < HB * Hn; i += 256) h_s[i] = 0.f;   // h0 = 0
    stage_weights(Wih_s, Whh_s, cr_s, cz_s, bin_s, bhn_s,
                  encWih, encWhh, encBih, encBhh, layer, isL0, tid);
    __syncthreads();

    for (int t = 0; t < 2 * Tn; ++t) {
        if (t == Tn) {   // encoder -> decoder: swap weights, keep h (= h_n)
            __syncthreads();
            stage_weights(Wih_s, Whh_s, cr_s, cz_s, bin_s, bhn_s,
                          decWih, decWhh, decBih, decBhh, layer, isL0, tid);
            __syncthreads();
        }
        // ---- sync: producer data ready / consumer slot free ----
        if (tid == 0) {
            if (layer > 0) {
                int tgt = base + t + 1;
                volatile int* p = &g_prog[cta - 2];
                while (*p < tgt) __nanosleep(64);
            }
            if (layer < Ln - 1 && t >= RINGN) {
                int tgt = base + t - RINGN + 1;
                volatile int* p = &g_prog[cta + 2];
                while (*p < tgt) __nanosleep(64);
            }
            __threadfence();
        }
        __syncthreads();

        // ---- stage input ----
        if (isL0) {
            int m  = (t < Tn) ? 0 : 1;
            int tt = (t < Tn) ? t : t - Tn;
            const float4* src = (const float4*)&g_gi0[m][tt][half * HB][0];
            float4* dst = (float4*)x_s;
            for (int i = tid; i < HB * G3H / 4; i += 256) dst[i] = src[i];
        } else {
            const float4* src =
                (const float4*)&g_xbuf[layer - 1][half][t & (RINGN - 1)][0][0];
            float4* dst = (float4*)x_s;
            for (int i = tid; i < HB * Hn / 4; i += 256) dst[i] = __ldcv(&src[i]);
        }
        __syncthreads();

        // ---- GEMMs (packed f32x2) ----
        u64 ar[8], az[8], an[8], ahn[8];
#pragma unroll
        for (int i = 0; i < 8; i++) {
            ar[i] = 0ull; az[i] = 0ull; an[i] = 0ull; ahn[i] = 0ull;
        }

        if (!isL0) {
            for (int k0 = 0; k0 < Hn; k0 += 4) {
                u64 wr[4], wz[4], wn[4], ur[4], uz[4], un[4];
#pragma unroll
                for (int kk = 0; kk < 4; kk++) {
                    const float* a = &Wih_s[(k0 + kk) * WSTR];
                    const float* b = &Whh_s[(k0 + kk) * WSTR];
                    wr[kk] = ld2(&a[jj]);
                    wz[kk] = ld2(&a[64 + jj]);
                    wn[kk] = ld2(&a[128 + jj]);
                    ur[kk] = ld2(&b[jj]);
                    uz[kk] = ld2(&b[64 + jj]);
                    un[kk] = ld2(&b[128 + jj]);
                }
#pragma unroll
                for (int i = 0; i < 8; i++) {
                    float4 xv = *(const float4*)&x_s[(bb + i) * Hn + k0];
                    float4 hv = *(const float4*)&h_s[(bb + i) * Hn + k0];
                    u64 xp[4] = {pack2(xv.x), pack2(xv.y),
                                 pack2(xv.z), pack2(xv.w)};
                    u64 hp[4] = {pack2(hv.x), pack2(hv.y),
                                 pack2(hv.z), pack2(hv.w)};
#pragma unroll
                    for (int kk = 0; kk < 4; kk++) {
                        fma2(ar[i], xp[kk], wr[kk]);
                        fma2(ar[i], hp[kk], ur[kk]);
                        fma2(az[i], xp[kk], wz[kk]);
                        fma2(az[i], hp[kk], uz[kk]);
                        fma2(an[i], xp[kk], wn[kk]);
                        fma2(ahn[i], hp[kk], un[kk]);
                    }
                }
            }
        } else {
            // layer 0: only h @ Whh^T (gi precomputed into x_s)
            for (int k0 = 0; k0 < Hn; k0 += 4) {
                u64 ur[4], uz[4], un[4];
#pragma unroll
                for (int kk = 0; kk < 4; kk++) {
                    const float* b = &Whh_s[(k0 + kk) * WSTR];
                    ur[kk] = ld2(&b[jj]);
                    uz[kk] = ld2(&b[64 + jj]);
                    un[kk] = ld2(&b[128 + jj]);
                }
#pragma unroll
                for (int i = 0; i < 8; i++) {
                    float4 hv = *(const float4*)&h_s[(bb + i) * Hn + k0];
                    u64 hp[4] = {pack2(hv.x), pack2(hv.y),
                                 pack2(hv.z), pack2(hv.w)};
#pragma unroll
                    for (int kk = 0; kk < 4; kk++) {
                        fma2(ar[i], hp[kk], ur[kk]);
                        fma2(az[i], hp[kk], uz[kk]);
                        fma2(ahn[i], hp[kk], un[kk]);
                    }
                }
            }
        }
        __syncthreads();   // all reads of h_s done before update

        // ---- epilogue: gates, h update, publish ----
        const bool wring = (layer < Ln - 1);
        const bool wtop  = (layer == Ln - 1) && (t >= Tn);
        float* rdst = &g_xbuf[layer][half][t & (RINGN - 1)][0][0];
        float* tdst = wtop ? &g_dectop[t - Tn][half * HB][0] : rdst;

#pragma unroll
        for (int i = 0; i < 8; i++) {
            int b = bb + i;
            float2 vr = unpack2(ar[i]);
            float2 vz = unpack2(az[i]);
            float2 vn = unpack2(an[i]);
            float2 vh = unpack2(ahn[i]);
            float arr[2] = {vr.x, vr.y}, azz[2] = {vz.x, vz.y};
            float ann[2] = {vn.x, vn.y}, ahh[2] = {vh.x, vh.y};
#pragma unroll
            for (int p = 0; p < 2; p++) {
                int hj = jj + p;
                float xr, xz, xn;
                if (isL0) {
                    xr = x_s[b * G3H + hj];
                    xz = x_s[b * G3H + 64 + hj];
                    xn = x_s[b * G3H + 128 + hj];
                } else {
                    xr = 0.f; xz = 0.f; xn = ann[p];
                }
                float r = sigf(arr[p] + xr + cr_s[hj]);
                float z = sigf(azz[p] + xz + cz_s[hj]);
                float n = tanhf_fast(xn + bin_s[hj] +
                                     r * (ahh[p] + bhn_s[hj]));
                float hold = h_s[b * Hn + hj];
                float hnew = (1.0f - z) * n + z * hold;
                h_s[b * Hn + hj] = hnew;
                if (wring) rdst[b * Hn + hj] = hnew;
                if (wtop)  tdst[b * Hn + hj] = hnew;
            }
        }
        __syncthreads();
        if (tid == 0) {
            __threadfence();
            *(volatile int*)&g_prog[cta] = base + t + 1;
        }
    }
}

// ---------------------------------------------------------------------------
// Kernel 3: output projection  out = dec_top @ Wo^T + bo. grid = (T, 2).
// ---------------------------------------------------------------------------
#define PSTR 130
#define PROJ_SMEM ((Hn * PSTR + HB * Hn) * 4)

__global__ void __launch_bounds__(256, 1) proj_kernel(
    const float* __restrict__ Wo, const float* __restrict__ bo,
    float* __restrict__ out)
{
    extern __shared__ float sm[];
    float* W_s = sm;                 // [64][PSTR] transposed: W_s[k*PSTR + d]
    float* x_s = W_s + Hn * PSTR;    // [HB][Hn]

    const int t = blockIdx.x, half = blockIdx.y;
    const int tid = threadIdx.x;
    const int warp = tid >> 5, lane = tid & 31;
    const int bb = warp * 8, jj = lane * 2;

    for (int idx = tid; idx < Dn * Hn; idx += 256) {
        int d = idx >> 6, k = idx & 63;
        W_s[k * PSTR + d] = Wo[idx];
    }
    for (int idx = tid; idx < HB * Hn; idx += 256) {
        x_s[idx] = g_dectop[t][half * HB + (idx >> 6)][idx & 63];
    }
    __syncthreads();

    u64 a0[8], a1[8];
#pragma unroll
    for (int i = 0; i < 8; i++) { a0[i] = 0ull; a1[i] = 0ull; }

    for (int k0 = 0; k0 < Hn; k0 += 4) {
        u64 w0[4], w1[4];
#pragma unroll
        for (int kk = 0; kk < 4; kk++) {
            const float* wrow = &W_s[(k0 + kk) * PSTR];
            w0[kk] = ld2(&wrow[jj]);
            w1[kk] = ld2(&wrow[64 + jj]);
        }
#pragma unroll
        for (int i = 0; i < 8; i++) {
            float4 xv = *(const float4*)&x_s[(bb + i) * Hn + k0];
            u64 xp[4] = {pack2(xv.x), pack2(xv.y), pack2(xv.z), pack2(xv.w)};
#pragma unroll
            for (int kk = 0; kk < 4; kk++) {
                fma2(a0[i], xp[kk], w0[kk]);
                fma2(a1[i], xp[kk], w1[kk]);
            }
        }
    }
    float2 b0 = *(const float2*)&bo[jj];
    float2 b1 = *(const float2*)&bo[64 + jj];
#pragma unroll
    for (int i = 0; i < 8; i++) {
        int bg = half * HB + bb + i;
        float* o = &out[((size_t)bg * Tn + t) * Dn];
        float2 v0 = unpack2(a0[i]), v1 = unpack2(a1[i]);
        *(float2*)&o[jj]      = make_float2(v0.x + b0.x, v0.y + b0.y);
        *(float2*)&o[64 + jj] = make_float2(v1.x + b1.x, v1.y + b1.y);
    }
}

// ---------------------------------------------------------------------------
extern "C" void kernel_launch(void* const* d_in, const int* in_sizes, int n_in,
                              void* d_out, int out_size) {
    const float* ctx     = (const float*)d_in[0];
    const float* encW0   = (const float*)d_in[1];
    const float* encWih  = (const float*)d_in[2];
    const float* encWhh  = (const float*)d_in[3];
    const float* encBih  = (const float*)d_in[4];
    const float* encBhh  = (const float*)d_in[5];
    const float* decW0   = (const float*)d_in[6];
    const float* decWih  = (const float*)d_in[7];
    const float* decWhh  = (const float*)d_in[8];
    const float* decBih  = (const float*)d_in[9];
    const float* decBhh  = (const float*)d_in[10];
    const float* Wo      = (const float*)d_in[11];
    const float* bo      = (const float*)d_in[12];
    float* out = (float*)d_out;

    cudaFuncSetAttribute(gi0_kernel,
        cudaFuncAttributeMaxDynamicSharedMemorySize, GI0_SMEM);
    cudaFuncSetAttribute(gru_wave,
        cudaFuncAttributeMaxDynamicSharedMemorySize, WAVE_SMEM);
    cudaFuncSetAttribute(proj_kernel,
        cudaFuncAttributeMaxDynamicSharedMemorySize, PROJ_SMEM);

    gi0_kernel<<<dim3(Tn, 2, 2), 256, GI0_SMEM>>>(ctx, encW0, decW0,
                                                  encBih, decBih);
    gru_wave<<<Ln * 2, 256, WAVE_SMEM>>>(encWih, encWhh, encBih, encBhh,
                                         decWih, decWhh, decBih, decBhh);
    proj_kernel<<<dim3(Tn, 2), 256, PROJ_SMEM>>>(Wo, bo, out);
}